// round 2
// baseline (speedup 1.0000x reference)
#include <cuda_runtime.h>
#include <math.h>

#define Bsz 256
#define Lsz 256
#define Dsz 128
#define Hh  2
#define Esz 64
#define NLay 2
#define TOPK 5

// ---------------- scratch (static device memory; no allocation) ----------------
__device__ float d_x   [Bsz*Lsz*Dsz];        // activations (B,L,D)
__device__ float d_qkv [Bsz*Lsz*3*Dsz];      // q|k|v cols 0/128/256, ld=384
__device__ float d_fqkv[Bsz*Lsz*3*Dsz];      // band-filtered q|k|v
__device__ float d_S   [Bsz*Hh*Lsz*Lsz];     // raw scores then softmaxed attn
__device__ float d_comb[Bsz*Lsz*Dsz];        // 0.9*freq + 0.1*spatial
__device__ float d_abuf[Bsz*Lsz*Dsz];        // attn output after Wp+residual
__device__ float d_hbuf[Bsz*Lsz*2*Dsz];      // FFN hidden
__device__ float d_P   [NLay*Lsz*Lsz];       // band-projection matrices
__device__ float d_mv  [Bsz*Lsz];            // mean_value
__device__ int   d_delays[TOPK];
__device__ float d_tc  [Bsz*TOPK];           // tmp_corr
__device__ float d_maskv[Bsz*Lsz];           // additive mask

// ---------------- helpers ----------------
__device__ __forceinline__ float gelu_f(float v){
    return v * 0.5f * (1.0f + erff(v * 0.70710678118654752f));
}

// ---------------- band-projection matrix P_k ----------------
// P[n,m] = (1/L) * sum_{f=l}^{r-1} w_f cos(2*pi*f*(n-m)/L), w=1 at f=0 or L/2 else 2
__global__ void compute_P_kernel(){
    __shared__ float ct[256];
    int k = blockIdx.x >> 8;
    int n = blockIdx.x & 255;
    int m = threadIdx.x;
    ct[m] = cospif((float)m / 128.0f);   // cos(2*pi*m/256)
    __syncthreads();
    int lft = (k == 0) ? 51 : 0;
    int rgt = (k == 0) ? 129 : 78;
    int dnm = n - m;
    float s = 0.f;
    for (int f = lft; f < rgt; f++){
        float w = (f == 0 || f == 128) ? 1.f : 2.f;
        s += w * ct[(f * dnm) & 255];
    }
    d_P[(k*256 + n)*256 + m] = s * (1.0f/256.0f);
}

// ---------------- embedding + mask ----------------
__global__ void embed_kernel(const int* __restrict__ paths,
                             const float* __restrict__ ego,
                             const float* __restrict__ pos){
    int bl = blockIdx.x;
    int d  = threadIdx.x;
    int p  = paths[bl];
    d_x[(long long)bl*128 + d] = ego[(long long)p*128 + d] + pos[(bl & 255)*128 + d];
    if (d == 0) d_maskv[bl] = (p < 100000) ? 0.f : -10000.f;
}

// ---------------- generic tiled GEMM: C(MxN) = alpha*A(MxK)*B + epi ----------------
// EPI: 0 plain, 1 += X (residual), 2 gelu, 3 C += alpha*AB (accumulate)
// TB : B is (N x K) row-major (C = A * B^T)
// batching: z -> (bb = z/Hdim, hh = z%Hdim), pointer offsets via strides.
template<int EPI, bool TB>
__global__ void __launch_bounds__(256, 2) gemm_k(
    const float* __restrict__ Ag, const float* __restrict__ Bg,
    float* __restrict__ Cg, const float* __restrict__ Xg,
    int M, int N, int K, int lda, int ldb, int ldc,
    long long sAb, long long sAh, long long sBb, long long sBh,
    long long sCb, long long sCh, int Hdim, float alpha)
{
    int z  = blockIdx.z;
    int bb = z / Hdim, hh = z - bb*Hdim;
    const float* A = Ag + bb*sAb + hh*sAh;
    const float* Bm = Bg + bb*sBb + hh*sBh;
    float* C = Cg + bb*sCb + hh*sCh;

    int m0 = blockIdx.y * 128;
    int n0 = blockIdx.x * 64;
    int tid = threadIdx.x;
    int tx = tid & 15;     // N
    int ty = tid >> 4;     // M (8 rows)

    __shared__ float As[16][132];
    __shared__ float Bs[16][68];

    float acc[8][4];
    #pragma unroll
    for (int i = 0; i < 8; i++)
        #pragma unroll
        for (int j = 0; j < 4; j++) acc[i][j] = 0.f;

    int am = tid >> 1;            // 0..127
    int ak = (tid & 1) * 8;       // 0 or 8
    int bkn, bkk;
    if (!TB){ bkk = tid >> 4; bkn = (tid & 15) * 4; }
    else    { bkn = tid >> 2; bkk = (tid & 3) * 4; }

    for (int k0 = 0; k0 < K; k0 += 16){
        float4 a0 = *(const float4*)(A + (long long)(m0+am)*lda + k0 + ak);
        float4 a1 = *(const float4*)(A + (long long)(m0+am)*lda + k0 + ak + 4);
        As[ak+0][am]=a0.x; As[ak+1][am]=a0.y; As[ak+2][am]=a0.z; As[ak+3][am]=a0.w;
        As[ak+4][am]=a1.x; As[ak+5][am]=a1.y; As[ak+6][am]=a1.z; As[ak+7][am]=a1.w;
        if (!TB){
            float4 b0 = *(const float4*)(Bm + (long long)(k0+bkk)*ldb + n0 + bkn);
            *(float4*)&Bs[bkk][bkn] = b0;
        } else {
            float4 b0 = *(const float4*)(Bm + (long long)(n0+bkn)*ldb + k0 + bkk);
            Bs[bkk+0][bkn]=b0.x; Bs[bkk+1][bkn]=b0.y; Bs[bkk+2][bkn]=b0.z; Bs[bkk+3][bkn]=b0.w;
        }
        __syncthreads();
        #pragma unroll
        for (int kk = 0; kk < 16; kk++){
            float4 b4 = *(const float4*)&Bs[kk][tx*4];
            float4 aa = *(const float4*)&As[kk][ty*8];
            float4 ab = *(const float4*)&As[kk][ty*8 + 4];
            float av[8] = {aa.x,aa.y,aa.z,aa.w, ab.x,ab.y,ab.z,ab.w};
            float bv[4] = {b4.x,b4.y,b4.z,b4.w};
            #pragma unroll
            for (int i = 0; i < 8; i++)
                #pragma unroll
                for (int j = 0; j < 4; j++)
                    acc[i][j] += av[i]*bv[j];
        }
        __syncthreads();
    }

    #pragma unroll
    for (int i = 0; i < 8; i++){
        long long crow = (long long)(m0 + ty*8 + i) * ldc + n0 + tx*4;
        float4 r;
        r.x = acc[i][0]*alpha; r.y = acc[i][1]*alpha;
        r.z = acc[i][2]*alpha; r.w = acc[i][3]*alpha;
        if (EPI == 1){
            float4 xv = *(const float4*)&Xg[crow];
            r.x += xv.x; r.y += xv.y; r.z += xv.z; r.w += xv.w;
        }
        if (EPI == 2){
            r.x = gelu_f(r.x); r.y = gelu_f(r.y); r.z = gelu_f(r.z); r.w = gelu_f(r.w);
        }
        if (EPI == 3){
            float4 cv = *(const float4*)&C[crow];
            r.x += cv.x; r.y += cv.y; r.z += cv.z; r.w += cv.w;
        }
        *(float4*)&C[crow] = r;
    }
}

// ---------------- circular-diagonal sums of raw scores -> mean_value ----------------
// mv[b,n] = (1/128) * sum_h sum_{i,t : (i-t)%L==n} S[b,h,i,t]
__global__ void __launch_bounds__(256) diag_sum_kernel(){
    int b = blockIdx.x;
    __shared__ float acc[8][256];
    int tid = threadIdx.x;
    int warp = tid >> 5, lane = tid & 31;
    for (int i = tid; i < 8*256; i += 256) ((float*)acc)[i] = 0.f;
    __syncthreads();
    for (int h = 0; h < 2; h++){
        const float* S = d_S + ((long long)(b*2 + h)) * 65536;
        for (int i = warp; i < 256; i += 8){
            const float* row = S + i*256;
            #pragma unroll
            for (int c = 0; c < 8; c++){
                int t = c*32 + lane;
                acc[warp][(i - t) & 255] += row[t];   // lanes hit distinct slots
            }
        }
    }
    __syncthreads();
    float s = 0.f;
    #pragma unroll
    for (int w = 0; w < 8; w++) s += acc[w][tid];
    d_mv[b*256 + tid] = s * (1.0f/128.0f);
}

// ---------------- global top-5 over mean over B ----------------
__global__ void topk_kernel(){
    int n = threadIdx.x;
    float s = 0.f;
    for (int b = 0; b < 256; b++) s += d_mv[b*256 + n];
    __shared__ float sg[256];
    sg[n] = s;
    __syncthreads();
    if (n == 0){
        for (int t = 0; t < TOPK; t++){
            int bi = 0; float bv = sg[0];
            for (int i = 1; i < 256; i++) if (sg[i] > bv){ bv = sg[i]; bi = i; }
            d_delays[t] = bi;
            sg[bi] = -1e30f;
        }
    }
}

// ---------------- per-batch softmax over the 5 selected weights ----------------
__global__ void weights_kernel(){
    int b = blockIdx.x;
    if (threadIdx.x == 0){
        float w[TOPK]; float mx = -1e30f;
        #pragma unroll
        for (int t = 0; t < TOPK; t++){ w[t] = d_mv[b*256 + d_delays[t]]; mx = fmaxf(mx, w[t]); }
        float s = 0.f;
        #pragma unroll
        for (int t = 0; t < TOPK; t++){ w[t] = expf(w[t]-mx); s += w[t]; }
        #pragma unroll
        for (int t = 0; t < TOPK; t++) d_tc[b*TOPK + t] = w[t]/s;
    }
}

// ---------------- attention softmax (in place, scale + mask) ----------------
__global__ void __launch_bounds__(256) softmax_kernel(){
    int row = blockIdx.x;           // (b*2+h)*256 + i
    int b = row >> 9;
    int j = threadIdx.x;
    float v = d_S[(long long)row*256 + j] * 0.125f + d_maskv[b*256 + j];
    __shared__ float red[256];
    red[j] = v; __syncthreads();
    for (int s = 128; s > 0; s >>= 1){ if (j < s) red[j] = fmaxf(red[j], red[j+s]); __syncthreads(); }
    float mx = red[0]; __syncthreads();
    float e = expf(v - mx);
    red[j] = e; __syncthreads();
    for (int s = 128; s > 0; s >>= 1){ if (j < s) red[j] += red[j+s]; __syncthreads(); }
    d_S[(long long)row*256 + j] = e / red[0];
}

// ---------------- freq branch: comb = 0.9 * sum_t v[(l+delay_t)%L] * tc[b,t] ----------------
__global__ void freq_kernel(){
    int bl = blockIdx.x*2 + (threadIdx.x >> 7);
    int d  = threadIdx.x & 127;
    int b  = bl >> 8, l = bl & 255;
    float s = 0.f;
    #pragma unroll
    for (int t = 0; t < TOPK; t++){
        int ll = (l + d_delays[t]) & 255;
        s += d_qkv[((long long)(b*256 + ll))*384 + 256 + d] * d_tc[b*TOPK + t];
    }
    d_comb[(long long)bl*128 + d] = 0.9f * s;
}

// ---------------- final gather ----------------
__global__ void gather_kernel(const int* __restrict__ lengths, float* __restrict__ out){
    int b = blockIdx.x, d = threadIdx.x;
    int l = lengths[b] - 1;
    out[b*128 + d] = d_x[((long long)b*256 + l)*128 + d];
}

// ---------------- host launch ----------------
extern "C" void kernel_launch(void* const* d_in, const int* in_sizes, int n_in,
                              void* d_out, int out_size)
{
    (void)in_sizes; (void)n_in; (void)out_size;
    const int*   paths   = (const int*)  d_in[0];
    const int*   lengths = (const int*)  d_in[1];
    const float* ego     = (const float*)d_in[4];
    const float* pos     = (const float*)d_in[5];
    const float* Wq      = (const float*)d_in[6];
    const float* Wk      = (const float*)d_in[7];
    const float* Wv      = (const float*)d_in[8];
    const float* Wp      = (const float*)d_in[9];
    const float* F1      = (const float*)d_in[10];
    const float* F2      = (const float*)d_in[11];
    float* out = (float*)d_out;

    float *px, *pqkv, *pfqkv, *pS, *pcomb, *pa, *ph, *pP;
    cudaGetSymbolAddress((void**)&px,    d_x);
    cudaGetSymbolAddress((void**)&pqkv,  d_qkv);
    cudaGetSymbolAddress((void**)&pfqkv, d_fqkv);
    cudaGetSymbolAddress((void**)&pS,    d_S);
    cudaGetSymbolAddress((void**)&pcomb, d_comb);
    cudaGetSymbolAddress((void**)&pa,    d_abuf);
    cudaGetSymbolAddress((void**)&ph,    d_hbuf);
    cudaGetSymbolAddress((void**)&pP,    d_P);

    compute_P_kernel<<<NLay*256, 256>>>();
    embed_kernel<<<Bsz*Lsz, 128>>>(paths, ego, pos);

    const int ML = Bsz*Lsz;   // 65536

    for (int k = 0; k < NLay; k++){
        const float* wq = Wq + k*Dsz*Dsz;
        const float* wk = Wk + k*Dsz*Dsz;
        const float* wv = Wv + k*Dsz*Dsz;
        const float* wp = Wp + k*Dsz*Dsz;
        const float* f1 = F1 + k*Dsz*2*Dsz;
        const float* f2 = F2 + k*2*Dsz*Dsz;

        // q,k,v projections: (65536x128x128) into strided qkv (ld=384)
        dim3 gp(2, ML/128, 1);
        gemm_k<0,false><<<gp,256>>>(px, wq, pqkv+0,   nullptr, ML,128,128, 128,128,384, 0,0,0,0,0,0, 1, 1.f);
        gemm_k<0,false><<<gp,256>>>(px, wk, pqkv+128, nullptr, ML,128,128, 128,128,384, 0,0,0,0,0,0, 1, 1.f);
        gemm_k<0,false><<<gp,256>>>(px, wv, pqkv+256, nullptr, ML,128,128, 128,128,384, 0,0,0,0,0,0, 1, 1.f);

        // band filter: fqkv[b] = P_k (256x256) @ qkv[b] (256x384), batched over b
        dim3 gf(6, 2, Bsz);
        gemm_k<0,false><<<gf,256>>>(pP + k*65536, pqkv, pfqkv, nullptr,
                                    256,384,256, 256,384,384,
                                    0,0, 98304,0, 98304,0, 1, 1.f);

        // raw scores: S[b,h] = q~ (256x64) @ k~^T, batched over (b,h)
        dim3 gs(4, 2, Bsz*Hh);
        gemm_k<0,true><<<gs,256>>>(pfqkv, pfqkv+128, pS, nullptr,
                                   256,256,64, 384,384,256,
                                   98304,64, 98304,64, 131072,65536, 2, 1.f);

        diag_sum_kernel<<<256,256>>>();
        topk_kernel<<<1,256>>>();
        weights_kernel<<<256,32>>>();
        softmax_kernel<<<Bsz*Hh*Lsz, 256>>>();
        freq_kernel<<<Bsz*Lsz/2, 256>>>();

        // spatial: comb += 0.1 * att (256x256) @ v~ (256x64), batched over (b,h)
        dim3 gsp(1, 2, Bsz*Hh);
        gemm_k<3,false><<<gsp,256>>>(pS, pfqkv+256, pcomb, nullptr,
                                     256,64,256, 256,384,128,
                                     131072,65536, 98304,64, 32768,64, 2, 0.1f);

        // a = comb @ Wp + x
        gemm_k<1,false><<<gp,256>>>(pcomb, wp, pa, px, ML,128,128, 128,128,128, 0,0,0,0,0,0, 1, 1.f);

        // FFN1 + GELU: h = gelu(a @ F1)
        dim3 g1(4, ML/128, 1);
        gemm_k<2,false><<<g1,256>>>(pa, f1, ph, nullptr, ML,256,128, 128,256,256, 0,0,0,0,0,0, 1, 1.f);

        // FFN2: x = h @ F2
        gemm_k<0,false><<<gp,256>>>(ph, f2, px, nullptr, ML,128,256, 256,128,128, 0,0,0,0,0,0, 1, 1.f);
    }

    gather_kernel<<<Bsz, 128>>>(lengths, out);
}

// round 3
// speedup vs baseline: 1.3448x; 1.3448x over previous
#include <cuda_runtime.h>
#include <math.h>
#include <stdint.h>

#define Bsz 256
#define Lsz 256
#define Dsz 128
#define Hh  2
#define Esz 64
#define NLay 2
#define TOPK 5

// ---------------- scratch (static device memory; no allocation) ----------------
__device__ float d_x   [Bsz*Lsz*Dsz];        // activations (B,L,D)
__device__ float d_qkv [Bsz*Lsz*3*Dsz];      // q|k|v cols 0/128/256, ld=384
__device__ float d_fqkv[Bsz*Lsz*3*Dsz];      // band-filtered q|k|v
__device__ float d_S   [Bsz*Hh*Lsz*Lsz];     // raw scores then softmaxed attn
__device__ float d_comb[Bsz*Lsz*Dsz];        // 0.9*freq + 0.1*spatial
__device__ float d_abuf[Bsz*Lsz*Dsz];        // attn output after Wp+residual
__device__ float d_hbuf[Bsz*Lsz*2*Dsz];      // FFN hidden
__device__ float d_P   [NLay*Lsz*Lsz];       // band-projection matrices
__device__ float d_Wcat[Dsz*3*Dsz];          // concatenated Wq|Wk|Wv (128x384)
__device__ float d_mv  [Bsz*Lsz];            // mean_value
__device__ int   d_delays[TOPK];
__device__ float d_tc  [Bsz*TOPK];           // tmp_corr
__device__ float d_maskv[Bsz*Lsz];           // additive mask

// ---------------- helpers ----------------
__device__ __forceinline__ float gelu_f(float v){
    return v * 0.5f * (1.0f + erff(v * 0.70710678118654752f));
}
__device__ __forceinline__ unsigned smem_u32(const void* p){
    return (unsigned)__cvta_generic_to_shared(p);
}
__device__ __forceinline__ void cp16(unsigned s, const float* g){
    asm volatile("cp.async.ca.shared.global [%0], [%1], 16;\n" :: "r"(s), "l"(g));
}
__device__ __forceinline__ uint32_t tf_hi(float x){
    return __float_as_uint(x) & 0xFFFFE000u;          // truncate to tf32; remainder exact
}
__device__ __forceinline__ uint32_t tf_lo(float x, uint32_t hi){
    return __float_as_uint(x - __uint_as_float(hi));
}
__device__ __forceinline__ void mma8(float* c, const uint32_t* a, const uint32_t* b){
    asm volatile(
      "mma.sync.aligned.m16n8k8.row.col.f32.tf32.tf32.f32 "
      "{%0,%1,%2,%3}, {%4,%5,%6,%7}, {%8,%9}, {%0,%1,%2,%3};\n"
      : "+f"(c[0]), "+f"(c[1]), "+f"(c[2]), "+f"(c[3])
      : "r"(a[0]), "r"(a[1]), "r"(a[2]), "r"(a[3]), "r"(b[0]), "r"(b[1]));
}

// ---------------- band-projection matrix P_k ----------------
__global__ void compute_P_kernel(){
    __shared__ float ct[256];
    int k = blockIdx.x >> 8;
    int n = blockIdx.x & 255;
    int m = threadIdx.x;
    ct[m] = cospif((float)m / 128.0f);   // cos(2*pi*m/256)
    __syncthreads();
    int lft = (k == 0) ? 51 : 0;
    int rgt = (k == 0) ? 129 : 78;
    int dnm = n - m;
    float s = 0.f;
    for (int f = lft; f < rgt; f++){
        float w = (f == 0 || f == 128) ? 1.f : 2.f;
        s += w * ct[(f * dnm) & 255];
    }
    d_P[(k*256 + n)*256 + m] = s * (1.0f/256.0f);
}

// ---------------- embedding + mask ----------------
__global__ void embed_kernel(const int* __restrict__ paths,
                             const float* __restrict__ ego,
                             const float* __restrict__ pos){
    int bl = blockIdx.x;
    int d  = threadIdx.x;
    int p  = paths[bl];
    d_x[(long long)bl*128 + d] = ego[(long long)p*128 + d] + pos[(bl & 255)*128 + d];
    if (d == 0) d_maskv[bl] = (p < 100000) ? 0.f : -10000.f;
}

// ---------------- pack Wq|Wk|Wv into one 128x384 matrix ----------------
__global__ void packW_kernel(const float* __restrict__ wq,
                             const float* __restrict__ wk,
                             const float* __restrict__ wv){
    int i = blockIdx.x*256 + threadIdx.x;      // 49152 total
    int r = i / 384, c = i % 384;
    const float* src = (c < 128) ? wq : ((c < 256) ? wk : wv);
    d_Wcat[i] = src[r*128 + (c & 127)];
}

// ---------------- tensor-core GEMM (tf32x3): C(MxBN tiles) = alpha*A*B + epi ----------
// EPI: 0 plain, 1 +=X residual, 2 gelu, 3 C += alpha*AB
// TB : B is (N x K) row-major
template<int EPI, bool TB, int BN>
__global__ void __launch_bounds__(256) gemm_tc(
    const float* __restrict__ Ag, const float* __restrict__ Bg,
    float* __restrict__ Cg, const float* __restrict__ Xg,
    int M, int N, int K, int lda, int ldb, int ldc,
    long long sAb, long long sAh, long long sBb, long long sBh,
    long long sCb, long long sCh, int Hdim, float alpha)
{
    constexpr int BM = 128, BK = 16;
    constexpr int AP  = 20;                     // A smem row stride (floats)
    constexpr int BNP = BN + 8;                 // B smem row stride non-TB
    constexpr int BSS = TB ? BN*20 : BK*BNP;    // B stage size
    constexpr int WCOLS = (BN == 128) ? 4 : 2;
    constexpr int WM    = (BN == 128) ? 64 : 32;
    constexpr int MT = WM / 16;
    constexpr int NT = 4;

    __shared__ float As[2][BM*AP];
    __shared__ float Bs[2][BSS];

    int z  = blockIdx.z;
    int bb = z / Hdim, hh = z - bb*Hdim;
    const float* A  = Ag + bb*sAb + hh*sAh;
    const float* Bm = Bg + bb*sBb + hh*sBh;
    float* C = Cg + bb*sCb + hh*sCh;

    int m0 = blockIdx.y * BM;
    int n0 = blockIdx.x * BN;
    int tid = threadIdx.x;
    int warp = tid >> 5, lane = tid & 31;
    int wm = warp / WCOLS, wn = warp % WCOLS;
    int wm0 = wm*WM, wn0 = wn*32;
    int g4 = lane >> 2, tg = lane & 3;

    float acc[MT][NT][4];
    #pragma unroll
    for (int i = 0; i < MT; i++)
        #pragma unroll
        for (int j = 0; j < NT; j++)
            #pragma unroll
            for (int r = 0; r < 4; r++) acc[i][j][r] = 0.f;

    const int KT = K / BK;

    // ---- stage loaders ----
    #define LOAD_A(st, k0) {                                                      \
        _Pragma("unroll")                                                         \
        for (int c = tid; c < BM*BK/4; c += 256){                                 \
            int row = c >> 2, kc = (c & 3) * 4;                                   \
            cp16(smem_u32(&As[st][row*AP + kc]),                                  \
                 A + (long long)(m0+row)*lda + (k0) + kc);                        \
        } }
    #define LOAD_B(st, k0) {                                                      \
        if (TB){                                                                  \
            _Pragma("unroll")                                                     \
            for (int c = tid; c < BN*BK/4; c += 256){                             \
                int row = c >> 2, kc = (c & 3)*4;                                 \
                cp16(smem_u32(&Bs[st][row*20 + kc]),                              \
                     Bm + (long long)(n0+row)*ldb + (k0) + kc);                   \
            }                                                                     \
        } else {                                                                  \
            constexpr int NCH = BN/4;                                             \
            _Pragma("unroll")                                                     \
            for (int c = tid; c < BK*NCH; c += 256){                              \
                int row = c / NCH, nc = (c % NCH)*4;                              \
                cp16(smem_u32(&Bs[st][row*BNP + nc]),                             \
                     Bm + (long long)((k0)+row)*ldb + n0 + nc);                   \
            }                                                                     \
        } }

    LOAD_A(0, 0); LOAD_B(0, 0);
    asm volatile("cp.async.commit_group;\n");

    for (int kt = 0; kt < KT; kt++){
        int cur = kt & 1;
        if (kt + 1 < KT){
            int nxt = (kt + 1) & 1;
            LOAD_A(nxt, (kt+1)*BK); LOAD_B(nxt, (kt+1)*BK);
            asm volatile("cp.async.commit_group;\n");
            asm volatile("cp.async.wait_group 1;\n");
        } else {
            asm volatile("cp.async.wait_group 0;\n");
        }
        __syncthreads();

        #pragma unroll
        for (int kk = 0; kk < BK; kk += 8){
            uint32_t Ah[MT][4], Al[MT][4], Bh[NT][2], Bl[NT][2];
            #pragma unroll
            for (int i = 0; i < MT; i++){
                int r = wm0 + i*16 + g4;
                int cidx = kk + tg;
                float f0 = As[cur][r*AP + cidx];
                float f1 = As[cur][(r+8)*AP + cidx];
                float f2 = As[cur][r*AP + cidx + 4];
                float f3 = As[cur][(r+8)*AP + cidx + 4];
                Ah[i][0]=tf_hi(f0); Al[i][0]=tf_lo(f0,Ah[i][0]);
                Ah[i][1]=tf_hi(f1); Al[i][1]=tf_lo(f1,Ah[i][1]);
                Ah[i][2]=tf_hi(f2); Al[i][2]=tf_lo(f2,Ah[i][2]);
                Ah[i][3]=tf_hi(f3); Al[i][3]=tf_lo(f3,Ah[i][3]);
            }
            #pragma unroll
            for (int j = 0; j < NT; j++){
                int n = wn0 + j*8 + g4;
                float b0, b1;
                if (TB){
                    b0 = Bs[cur][n*20 + kk + tg];
                    b1 = Bs[cur][n*20 + kk + tg + 4];
                } else {
                    b0 = Bs[cur][(kk + tg)*BNP + n];
                    b1 = Bs[cur][(kk + tg + 4)*BNP + n];
                }
                Bh[j][0]=tf_hi(b0); Bl[j][0]=tf_lo(b0,Bh[j][0]);
                Bh[j][1]=tf_hi(b1); Bl[j][1]=tf_lo(b1,Bh[j][1]);
            }
            #pragma unroll
            for (int i = 0; i < MT; i++)
                #pragma unroll
                for (int j = 0; j < NT; j++){
                    mma8(acc[i][j], Ah[i], Bh[j]);
                    mma8(acc[i][j], Ah[i], Bl[j]);
                    mma8(acc[i][j], Al[i], Bh[j]);
                }
        }
        __syncthreads();
    }

    // ---- epilogue ----
    #pragma unroll
    for (int i = 0; i < MT; i++)
        #pragma unroll
        for (int j = 0; j < NT; j++){
            int row = m0 + wm0 + i*16 + g4;
            int col = n0 + wn0 + j*8 + tg*2;
            #pragma unroll
            for (int h = 0; h < 2; h++){
                long long off = (long long)(row + h*8)*ldc + col;
                float2 r;
                r.x = acc[i][j][h*2+0]*alpha;
                r.y = acc[i][j][h*2+1]*alpha;
                if (EPI == 1){ float2 xv = *(const float2*)&Xg[off]; r.x += xv.x; r.y += xv.y; }
                if (EPI == 2){ r.x = gelu_f(r.x); r.y = gelu_f(r.y); }
                if (EPI == 3){ float2 cv = *(const float2*)&C[off]; r.x += cv.x; r.y += cv.y; }
                *(float2*)&C[off] = r;
            }
        }
    #undef LOAD_A
    #undef LOAD_B
}

// ---------------- circular-diagonal sums of raw scores -> mean_value ----------------
__global__ void __launch_bounds__(256) diag_sum_kernel(){
    int b = blockIdx.x;
    __shared__ float acc[8][256];
    int tid = threadIdx.x;
    int warp = tid >> 5, lane = tid & 31;
    for (int i = tid; i < 8*256; i += 256) ((float*)acc)[i] = 0.f;
    __syncthreads();
    for (int h = 0; h < 2; h++){
        const float* S = d_S + ((long long)(b*2 + h)) * 65536;
        for (int i = warp; i < 256; i += 8){
            const float* row = S + i*256;
            #pragma unroll
            for (int c = 0; c < 8; c++){
                int t = c*32 + lane;
                acc[warp][(i - t) & 255] += row[t];
            }
        }
    }
    __syncthreads();
    float s = 0.f;
    #pragma unroll
    for (int w = 0; w < 8; w++) s += acc[w][tid];
    d_mv[b*256 + tid] = s * (1.0f/128.0f);
}

// ---------------- global top-5 over mean over B ----------------
__global__ void topk_kernel(){
    int n = threadIdx.x;
    float s = 0.f;
    for (int b = 0; b < 256; b++) s += d_mv[b*256 + n];
    __shared__ float sg[256];
    sg[n] = s;
    __syncthreads();
    if (n == 0){
        for (int t = 0; t < TOPK; t++){
            int bi = 0; float bv = sg[0];
            for (int i = 1; i < 256; i++) if (sg[i] > bv){ bv = sg[i]; bi = i; }
            d_delays[t] = bi;
            sg[bi] = -1e30f;
        }
    }
}

// ---------------- per-batch softmax over the 5 selected weights ----------------
__global__ void weights_kernel(){
    int b = blockIdx.x;
    if (threadIdx.x == 0){
        float w[TOPK]; float mx = -1e30f;
        #pragma unroll
        for (int t = 0; t < TOPK; t++){ w[t] = d_mv[b*256 + d_delays[t]]; mx = fmaxf(mx, w[t]); }
        float s = 0.f;
        #pragma unroll
        for (int t = 0; t < TOPK; t++){ w[t] = expf(w[t]-mx); s += w[t]; }
        #pragma unroll
        for (int t = 0; t < TOPK; t++) d_tc[b*TOPK + t] = w[t]/s;
    }
}

// ---------------- attention softmax (in place, scale + mask) ----------------
__global__ void __launch_bounds__(256) softmax_kernel(){
    int row = blockIdx.x;           // (b*2+h)*256 + i
    int b = row >> 9;
    int j = threadIdx.x;
    float v = d_S[(long long)row*256 + j] * 0.125f + d_maskv[b*256 + j];
    __shared__ float red[256];
    red[j] = v; __syncthreads();
    for (int s = 128; s > 0; s >>= 1){ if (j < s) red[j] = fmaxf(red[j], red[j+s]); __syncthreads(); }
    float mx = red[0]; __syncthreads();
    float e = expf(v - mx);
    red[j] = e; __syncthreads();
    for (int s = 128; s > 0; s >>= 1){ if (j < s) red[j] += red[j+s]; __syncthreads(); }
    d_S[(long long)row*256 + j] = e / red[0];
}

// ---------------- freq branch: comb = 0.9 * sum_t v[(l+delay_t)%L] * tc[b,t] ----------------
__global__ void freq_kernel(){
    int bl = blockIdx.x*2 + (threadIdx.x >> 7);
    int d  = threadIdx.x & 127;
    int b  = bl >> 8, l = bl & 255;
    float s = 0.f;
    #pragma unroll
    for (int t = 0; t < TOPK; t++){
        int ll = (l + d_delays[t]) & 255;
        s += d_qkv[((long long)(b*256 + ll))*384 + 256 + d] * d_tc[b*TOPK + t];
    }
    d_comb[(long long)bl*128 + d] = 0.9f * s;
}

// ---------------- final gather ----------------
__global__ void gather_kernel(const int* __restrict__ lengths, float* __restrict__ out){
    int b = blockIdx.x, d = threadIdx.x;
    int l = lengths[b] - 1;
    out[b*128 + d] = d_x[((long long)b*256 + l)*128 + d];
}

// ---------------- host launch ----------------
extern "C" void kernel_launch(void* const* d_in, const int* in_sizes, int n_in,
                              void* d_out, int out_size)
{
    (void)in_sizes; (void)n_in; (void)out_size;
    const int*   paths   = (const int*)  d_in[0];
    const int*   lengths = (const int*)  d_in[1];
    const float* ego     = (const float*)d_in[4];
    const float* pos     = (const float*)d_in[5];
    const float* Wq      = (const float*)d_in[6];
    const float* Wk      = (const float*)d_in[7];
    const float* Wv      = (const float*)d_in[8];
    const float* Wp      = (const float*)d_in[9];
    const float* F1      = (const float*)d_in[10];
    const float* F2      = (const float*)d_in[11];
    float* out = (float*)d_out;

    float *px, *pqkv, *pfqkv, *pS, *pcomb, *pa, *ph, *pP, *pW;
    cudaGetSymbolAddress((void**)&px,    d_x);
    cudaGetSymbolAddress((void**)&pqkv,  d_qkv);
    cudaGetSymbolAddress((void**)&pfqkv, d_fqkv);
    cudaGetSymbolAddress((void**)&pS,    d_S);
    cudaGetSymbolAddress((void**)&pcomb, d_comb);
    cudaGetSymbolAddress((void**)&pa,    d_abuf);
    cudaGetSymbolAddress((void**)&ph,    d_hbuf);
    cudaGetSymbolAddress((void**)&pP,    d_P);
    cudaGetSymbolAddress((void**)&pW,    d_Wcat);

    compute_P_kernel<<<NLay*256, 256>>>();
    embed_kernel<<<Bsz*Lsz, 128>>>(paths, ego, pos);

    const int ML = Bsz*Lsz;   // 65536

    for (int k = 0; k < NLay; k++){
        const float* wq = Wq + k*Dsz*Dsz;
        const float* wk = Wk + k*Dsz*Dsz;
        const float* wv = Wv + k*Dsz*Dsz;
        const float* wp = Wp + k*Dsz*Dsz;
        const float* f1 = F1 + k*Dsz*2*Dsz;
        const float* f2 = F2 + k*2*Dsz*Dsz;

        // fused q|k|v projection: (65536 x 384 x 128)
        packW_kernel<<<192, 256>>>(wq, wk, wv);
        gemm_tc<0,false,128><<<dim3(3, ML/128, 1), 256>>>(
            px, pW, pqkv, nullptr, ML,384,128, 128,384,384,
            0,0,0,0,0,0, 1, 1.f);

        // band filter: fqkv[b] = P_k (256x256) @ qkv[b] (256x384)
        gemm_tc<0,false,128><<<dim3(3, 2, Bsz), 256>>>(
            pP + k*65536, pqkv, pfqkv, nullptr, 256,384,256, 256,384,384,
            0,0, 98304,0, 98304,0, 1, 1.f);

        // raw scores: S[b,h] = q~ (256x64) @ k~^T
        gemm_tc<0,true,128><<<dim3(2, 2, Bsz*Hh), 256>>>(
            pfqkv, pfqkv+128, pS, nullptr, 256,256,64, 384,384,256,
            98304,64, 98304,64, 131072,65536, 2, 1.f);

        diag_sum_kernel<<<256,256>>>();
        topk_kernel<<<1,256>>>();
        weights_kernel<<<256,32>>>();
        softmax_kernel<<<Bsz*Hh*Lsz, 256>>>();
        freq_kernel<<<Bsz*Lsz/2, 256>>>();

        // spatial: comb += 0.1 * att (256x256) @ v~ (256x64)
        gemm_tc<3,false,64><<<dim3(1, 2, Bsz*Hh), 256>>>(
            pS, pfqkv+256, pcomb, nullptr, 256,64,256, 256,384,128,
            131072,65536, 98304,64, 32768,64, 2, 0.1f);

        // a = comb @ Wp + x
        gemm_tc<1,false,128><<<dim3(1, ML/128, 1), 256>>>(
            pcomb, wp, pa, px, ML,128,128, 128,128,128,
            0,0,0,0,0,0, 1, 1.f);

        // FFN1 + GELU
        gemm_tc<2,false,128><<<dim3(2, ML/128, 1), 256>>>(
            pa, f1, ph, nullptr, ML,256,128, 128,256,256,
            0,0,0,0,0,0, 1, 1.f);

        // FFN2
        gemm_tc<0,false,128><<<dim3(1, ML/128, 1), 256>>>(
            ph, f2, px, nullptr, ML,128,256, 256,128,128,
            0,0,0,0,0,0, 1, 1.f);
    }

    gather_kernel<<<Bsz, 128>>>(lengths, out);
}

// round 4
// speedup vs baseline: 1.5153x; 1.1268x over previous
#include <cuda_runtime.h>
#include <math.h>
#include <stdint.h>

#define Bsz 256
#define Lsz 256
#define Dsz 128
#define Hh  2
#define Esz 64
#define NLay 2
#define TOPK 5

// ---------------- scratch (static device memory; no allocation) ----------------
__device__ float d_x   [Bsz*Lsz*Dsz];        // activations (B,L,D)
__device__ float d_qkv [Bsz*Lsz*3*Dsz];      // q|k|v cols 0/128/256, ld=384
__device__ float d_fqkv[Bsz*Lsz*3*Dsz];      // band-filtered q|k|v
__device__ float d_S   [Bsz*Hh*Lsz*Lsz];     // raw scores then softmaxed attn
__device__ float d_comb[Bsz*Lsz*Dsz];        // 0.9*freq + 0.1*spatial
__device__ float d_abuf[Bsz*Lsz*Dsz];        // attn output after Wp+residual
__device__ float d_hbuf[Bsz*Lsz*2*Dsz];      // FFN hidden
__device__ float d_P   [NLay*Lsz*Lsz];       // band-projection matrices
__device__ float d_Wcat[Dsz*3*Dsz];          // concatenated Wq|Wk|Wv (128x384)
__device__ float d_mv  [Bsz*Lsz];            // mean_value
__device__ int   d_delays[TOPK];
__device__ float d_tc  [Bsz*TOPK];           // tmp_corr
__device__ float d_maskv[Bsz*Lsz];           // additive mask

// ---------------- helpers ----------------
__device__ __forceinline__ float gelu_f(float v){
    return v * 0.5f * (1.0f + erff(v * 0.70710678118654752f));
}
__device__ __forceinline__ unsigned smem_u32(const void* p){
    return (unsigned)__cvta_generic_to_shared(p);
}
__device__ __forceinline__ void cp16(unsigned s, const float* g){
    asm volatile("cp.async.ca.shared.global [%0], [%1], 16;\n" :: "r"(s), "l"(g));
}
// split fp32 -> bf16 hi (truncate) + bf16 lo (truncated remainder), packed x2
__device__ __forceinline__ float hipart(float x){
    return __uint_as_float(__float_as_uint(x) & 0xFFFF0000u);
}
__device__ __forceinline__ uint32_t packbf(float x, float y){
    return (__float_as_uint(x) >> 16) | (__float_as_uint(y) & 0xFFFF0000u);
}
__device__ __forceinline__ void splitpack(float x, float y, uint32_t& h, uint32_t& l){
    float hx = hipart(x), hy = hipart(y);
    h = packbf(x, y);
    l = packbf(x - hx, y - hy);
}
__device__ __forceinline__ void mma16(float* c, const uint32_t* a, const uint32_t* b){
    asm volatile(
      "mma.sync.aligned.m16n8k16.row.col.f32.bf16.bf16.f32 "
      "{%0,%1,%2,%3}, {%4,%5,%6,%7}, {%8,%9}, {%0,%1,%2,%3};\n"
      : "+f"(c[0]), "+f"(c[1]), "+f"(c[2]), "+f"(c[3])
      : "r"(a[0]), "r"(a[1]), "r"(a[2]), "r"(a[3]), "r"(b[0]), "r"(b[1]));
}

// ---------------- band-projection matrix P_k ----------------
__global__ void compute_P_kernel(){
    __shared__ float ct[256];
    int k = blockIdx.x >> 8;
    int n = blockIdx.x & 255;
    int m = threadIdx.x;
    ct[m] = cospif((float)m / 128.0f);   // cos(2*pi*m/256)
    __syncthreads();
    int lft = (k == 0) ? 51 : 0;
    int rgt = (k == 0) ? 129 : 78;
    int dnm = n - m;
    float s = 0.f;
    for (int f = lft; f < rgt; f++){
        float w = (f == 0 || f == 128) ? 1.f : 2.f;
        s += w * ct[(f * dnm) & 255];
    }
    d_P[(k*256 + n)*256 + m] = s * (1.0f/256.0f);
}

// ---------------- embedding + mask ----------------
__global__ void embed_kernel(const int* __restrict__ paths,
                             const float* __restrict__ ego,
                             const float* __restrict__ pos){
    int bl = blockIdx.x;
    int d  = threadIdx.x;
    int p  = paths[bl];
    d_x[(long long)bl*128 + d] = ego[(long long)p*128 + d] + pos[(bl & 255)*128 + d];
    if (d == 0) d_maskv[bl] = (p < 100000) ? 0.f : -10000.f;
}

// ---------------- pack Wq|Wk|Wv into one 128x384 matrix ----------------
__global__ void packW_kernel(const float* __restrict__ wq,
                             const float* __restrict__ wk,
                             const float* __restrict__ wv){
    int i = blockIdx.x*256 + threadIdx.x;      // 49152 total
    int r = i / 384, c = i % 384;
    const float* src = (c < 128) ? wq : ((c < 256) ? wk : wv);
    d_Wcat[i] = src[r*128 + (c & 127)];
}

// ---------------- tensor-core GEMM (bf16x3): C = alpha*A*B + epi --------------
// EPI: 0 plain, 1 +=X residual, 2 gelu, 3 C += alpha*AB
// TB : B is (N x K) row-major
template<int EPI, bool TB, int BN>
__global__ void __launch_bounds__(256) gemm_tc(
    const float* __restrict__ Ag, const float* __restrict__ Bg,
    float* __restrict__ Cg, const float* __restrict__ Xg,
    int M, int N, int K, int lda, int ldb, int ldc,
    long long sAb, long long sAh, long long sBb, long long sBh,
    long long sCb, long long sCh, int Hdim, float alpha)
{
    constexpr int BM = 128, BK = 16;
    constexpr int AP  = 24;                     // A smem row stride (floats)
    constexpr int BNP = BN + 4;                 // B smem row stride non-TB
    constexpr int BSS = TB ? BN*24 : BK*BNP;    // B stage size (floats)
    constexpr int WCOLS = (BN == 128) ? 4 : 2;
    constexpr int WM    = (BN == 128) ? 64 : 32;
    constexpr int MT = WM / 16;
    constexpr int NT = 4;

    __shared__ float As[2][BM*AP];
    __shared__ float Bs[2][BSS];

    int z  = blockIdx.z;
    int bb = z / Hdim, hh = z - bb*Hdim;
    const float* A  = Ag + bb*sAb + hh*sAh;
    const float* Bm = Bg + bb*sBb + hh*sBh;
    float* C = Cg + bb*sCb + hh*sCh;

    int m0 = blockIdx.y * BM;
    int n0 = blockIdx.x * BN;
    int tid = threadIdx.x;
    int warp = tid >> 5, lane = tid & 31;
    int wm = warp / WCOLS, wn = warp % WCOLS;
    int wm0 = wm*WM, wn0 = wn*32;
    int g4 = lane >> 2, tg = lane & 3;

    float acc[MT][NT][4];
    #pragma unroll
    for (int i = 0; i < MT; i++)
        #pragma unroll
        for (int j = 0; j < NT; j++)
            #pragma unroll
            for (int r = 0; r < 4; r++) acc[i][j][r] = 0.f;

    const int KT = K / BK;

    // ---- stage loaders ----
    #define LOAD_A(st, k0) {                                                      \
        _Pragma("unroll")                                                         \
        for (int c = tid; c < BM*BK/4; c += 256){                                 \
            int row = c >> 2, kc = (c & 3) * 4;                                   \
            cp16(smem_u32(&As[st][row*AP + kc]),                                  \
                 A + (long long)(m0+row)*lda + (k0) + kc);                        \
        } }
    #define LOAD_B(st, k0) {                                                      \
        if (TB){                                                                  \
            _Pragma("unroll")                                                     \
            for (int c = tid; c < BN*BK/4; c += 256){                             \
                int row = c >> 2, kc = (c & 3)*4;                                 \
                cp16(smem_u32(&Bs[st][row*24 + kc]),                              \
                     Bm + (long long)(n0+row)*ldb + (k0) + kc);                   \
            }                                                                     \
        } else {                                                                  \
            constexpr int NCH = BN/4;                                             \
            _Pragma("unroll")                                                     \
            for (int c = tid; c < BK*NCH; c += 256){                              \
                int row = c / NCH, nc = (c % NCH)*4;                              \
                cp16(smem_u32(&Bs[st][row*BNP + nc]),                             \
                     Bm + (long long)((k0)+row)*ldb + n0 + nc);                   \
            }                                                                     \
        } }

    LOAD_A(0, 0); LOAD_B(0, 0);
    asm volatile("cp.async.commit_group;\n");

    for (int kt = 0; kt < KT; kt++){
        int cur = kt & 1;
        if (kt + 1 < KT){
            int nxt = (kt + 1) & 1;
            LOAD_A(nxt, (kt+1)*BK); LOAD_B(nxt, (kt+1)*BK);
            asm volatile("cp.async.commit_group;\n");
            asm volatile("cp.async.wait_group 1;\n");
        } else {
            asm volatile("cp.async.wait_group 0;\n");
        }
        __syncthreads();

        // one m16n8k16 fragment set covers the whole BK=16 tile
        uint32_t Ah[MT][4], Al[MT][4], Bh[NT][2], Bl[NT][2];
        #pragma unroll
        for (int i = 0; i < MT; i++){
            int r = wm0 + i*16 + g4;
            float2 p0 = *(const float2*)&As[cur][ r     *AP + 2*tg    ];
            float2 p1 = *(const float2*)&As[cur][(r + 8)*AP + 2*tg    ];
            float2 p2 = *(const float2*)&As[cur][ r     *AP + 2*tg + 8];
            float2 p3 = *(const float2*)&As[cur][(r + 8)*AP + 2*tg + 8];
            splitpack(p0.x, p0.y, Ah[i][0], Al[i][0]);
            splitpack(p1.x, p1.y, Ah[i][1], Al[i][1]);
            splitpack(p2.x, p2.y, Ah[i][2], Al[i][2]);
            splitpack(p3.x, p3.y, Ah[i][3], Al[i][3]);
        }
        #pragma unroll
        for (int j = 0; j < NT; j++){
            int n = wn0 + j*8 + g4;
            float b00, b01, b10, b11;
            if (TB){
                float2 q0 = *(const float2*)&Bs[cur][n*24 + 2*tg    ];
                float2 q1 = *(const float2*)&Bs[cur][n*24 + 2*tg + 8];
                b00 = q0.x; b01 = q0.y; b10 = q1.x; b11 = q1.y;
            } else {
                b00 = Bs[cur][(2*tg    )*BNP + n];
                b01 = Bs[cur][(2*tg + 1)*BNP + n];
                b10 = Bs[cur][(2*tg + 8)*BNP + n];
                b11 = Bs[cur][(2*tg + 9)*BNP + n];
            }
            splitpack(b00, b01, Bh[j][0], Bl[j][0]);
            splitpack(b10, b11, Bh[j][1], Bl[j][1]);
        }
        #pragma unroll
        for (int i = 0; i < MT; i++)
            #pragma unroll
            for (int j = 0; j < NT; j++){
                mma16(acc[i][j], Ah[i], Bh[j]);
                mma16(acc[i][j], Ah[i], Bl[j]);
                mma16(acc[i][j], Al[i], Bh[j]);
            }
        __syncthreads();
    }

    // ---- epilogue ----
    #pragma unroll
    for (int i = 0; i < MT; i++)
        #pragma unroll
        for (int j = 0; j < NT; j++){
            int row = m0 + wm0 + i*16 + g4;
            int col = n0 + wn0 + j*8 + tg*2;
            #pragma unroll
            for (int h = 0; h < 2; h++){
                long long off = (long long)(row + h*8)*ldc + col;
                float2 r;
                r.x = acc[i][j][h*2+0]*alpha;
                r.y = acc[i][j][h*2+1]*alpha;
                if (EPI == 1){ float2 xv = *(const float2*)&Xg[off]; r.x += xv.x; r.y += xv.y; }
                if (EPI == 2){ r.x = gelu_f(r.x); r.y = gelu_f(r.y); }
                if (EPI == 3){ float2 cv = *(const float2*)&C[off]; r.x += cv.x; r.y += cv.y; }
                *(float2*)&C[off] = r;
            }
        }
    #undef LOAD_A
    #undef LOAD_B
}

// ---------------- circular-diagonal sums of raw scores -> mean_value ----------------
__global__ void __launch_bounds__(256) diag_sum_kernel(){
    int b = blockIdx.x;
    __shared__ float acc[8][256];
    int tid = threadIdx.x;
    int warp = tid >> 5, lane = tid & 31;
    for (int i = tid; i < 8*256; i += 256) ((float*)acc)[i] = 0.f;
    __syncthreads();
    for (int h = 0; h < 2; h++){
        const float* S = d_S + ((long long)(b*2 + h)) * 65536;
        for (int i = warp; i < 256; i += 8){
            const float* row = S + i*256;
            #pragma unroll
            for (int c = 0; c < 8; c++){
                int t = c*32 + lane;
                acc[warp][(i - t) & 255] += row[t];
            }
        }
    }
    __syncthreads();
    float s = 0.f;
    #pragma unroll
    for (int w = 0; w < 8; w++) s += acc[w][tid];
    d_mv[b*256 + tid] = s * (1.0f/128.0f);
}

// ---------------- global top-5 over mean over B ----------------
__global__ void topk_kernel(){
    int n = threadIdx.x;
    float s = 0.f;
    for (int b = 0; b < 256; b++) s += d_mv[b*256 + n];
    __shared__ float sg[256];
    sg[n] = s;
    __syncthreads();
    if (n == 0){
        for (int t = 0; t < TOPK; t++){
            int bi = 0; float bv = sg[0];
            for (int i = 1; i < 256; i++) if (sg[i] > bv){ bv = sg[i]; bi = i; }
            d_delays[t] = bi;
            sg[bi] = -1e30f;
        }
    }
}

// ---------------- per-batch softmax over the 5 selected weights ----------------
__global__ void weights_kernel(){
    int b = blockIdx.x;
    if (threadIdx.x == 0){
        float w[TOPK]; float mx = -1e30f;
        #pragma unroll
        for (int t = 0; t < TOPK; t++){ w[t] = d_mv[b*256 + d_delays[t]]; mx = fmaxf(mx, w[t]); }
        float s = 0.f;
        #pragma unroll
        for (int t = 0; t < TOPK; t++){ w[t] = expf(w[t]-mx); s += w[t]; }
        #pragma unroll
        for (int t = 0; t < TOPK; t++) d_tc[b*TOPK + t] = w[t]/s;
    }
}

// ---------------- attention softmax (in place, scale + mask) ----------------
__global__ void __launch_bounds__(256) softmax_kernel(){
    int row = blockIdx.x;           // (b*2+h)*256 + i
    int b = row >> 9;
    int j = threadIdx.x;
    float v = d_S[(long long)row*256 + j] * 0.125f + d_maskv[b*256 + j];
    __shared__ float red[256];
    red[j] = v; __syncthreads();
    for (int s = 128; s > 0; s >>= 1){ if (j < s) red[j] = fmaxf(red[j], red[j+s]); __syncthreads(); }
    float mx = red[0]; __syncthreads();
    float e = expf(v - mx);
    red[j] = e; __syncthreads();
    for (int s = 128; s > 0; s >>= 1){ if (j < s) red[j] += red[j+s]; __syncthreads(); }
    d_S[(long long)row*256 + j] = e / red[0];
}

// ---------------- freq branch: comb = 0.9 * sum_t v[(l+delay_t)%L] * tc[b,t] ----------------
__global__ void freq_kernel(){
    int bl = blockIdx.x*2 + (threadIdx.x >> 7);
    int d  = threadIdx.x & 127;
    int b  = bl >> 8, l = bl & 255;
    float s = 0.f;
    #pragma unroll
    for (int t = 0; t < TOPK; t++){
        int ll = (l + d_delays[t]) & 255;
        s += d_qkv[((long long)(b*256 + ll))*384 + 256 + d] * d_tc[b*TOPK + t];
    }
    d_comb[(long long)bl*128 + d] = 0.9f * s;
}

// ---------------- final gather ----------------
__global__ void gather_kernel(const int* __restrict__ lengths, float* __restrict__ out){
    int b = blockIdx.x, d = threadIdx.x;
    int l = lengths[b] - 1;
    out[b*128 + d] = d_x[((long long)b*256 + l)*128 + d];
}

// ---------------- host launch ----------------
extern "C" void kernel_launch(void* const* d_in, const int* in_sizes, int n_in,
                              void* d_out, int out_size)
{
    (void)in_sizes; (void)n_in; (void)out_size;
    const int*   paths   = (const int*)  d_in[0];
    const int*   lengths = (const int*)  d_in[1];
    const float* ego     = (const float*)d_in[4];
    const float* pos     = (const float*)d_in[5];
    const float* Wq      = (const float*)d_in[6];
    const float* Wk      = (const float*)d_in[7];
    const float* Wv      = (const float*)d_in[8];
    const float* Wp      = (const float*)d_in[9];
    const float* F1      = (const float*)d_in[10];
    const float* F2      = (const float*)d_in[11];
    float* out = (float*)d_out;

    float *px, *pqkv, *pfqkv, *pS, *pcomb, *pa, *ph, *pP, *pW;
    cudaGetSymbolAddress((void**)&px,    d_x);
    cudaGetSymbolAddress((void**)&pqkv,  d_qkv);
    cudaGetSymbolAddress((void**)&pfqkv, d_fqkv);
    cudaGetSymbolAddress((void**)&pS,    d_S);
    cudaGetSymbolAddress((void**)&pcomb, d_comb);
    cudaGetSymbolAddress((void**)&pa,    d_abuf);
    cudaGetSymbolAddress((void**)&ph,    d_hbuf);
    cudaGetSymbolAddress((void**)&pP,    d_P);
    cudaGetSymbolAddress((void**)&pW,    d_Wcat);

    compute_P_kernel<<<NLay*256, 256>>>();
    embed_kernel<<<Bsz*Lsz, 128>>>(paths, ego, pos);

    const int ML = Bsz*Lsz;   // 65536

    for (int k = 0; k < NLay; k++){
        const float* wq = Wq + k*Dsz*Dsz;
        const float* wk = Wk + k*Dsz*Dsz;
        const float* wv = Wv + k*Dsz*Dsz;
        const float* wp = Wp + k*Dsz*Dsz;
        const float* f1 = F1 + k*Dsz*2*Dsz;
        const float* f2 = F2 + k*2*Dsz*Dsz;

        // fused q|k|v projection: (65536 x 384 x 128)
        packW_kernel<<<192, 256>>>(wq, wk, wv);
        gemm_tc<0,false,128><<<dim3(3, ML/128, 1), 256>>>(
            px, pW, pqkv, nullptr, ML,384,128, 128,384,384,
            0,0,0,0,0,0, 1, 1.f);

        // band filter: fqkv[b] = P_k (256x256) @ qkv[b] (256x384)
        gemm_tc<0,false,128><<<dim3(3, 2, Bsz), 256>>>(
            pP + k*65536, pqkv, pfqkv, nullptr, 256,384,256, 256,384,384,
            0,0, 98304,0, 98304,0, 1, 1.f);

        // raw scores: S[b,h] = q~ (256x64) @ k~^T
        gemm_tc<0,true,128><<<dim3(2, 2, Bsz*Hh), 256>>>(
            pfqkv, pfqkv+128, pS, nullptr, 256,256,64, 384,384,256,
            98304,64, 98304,64, 131072,65536, 2, 1.f);

        diag_sum_kernel<<<256,256>>>();
        topk_kernel<<<1,256>>>();
        weights_kernel<<<256,32>>>();
        softmax_kernel<<<Bsz*Hh*Lsz, 256>>>();
        freq_kernel<<<Bsz*Lsz/2, 256>>>();

        // spatial: comb += 0.1 * att (256x256) @ v~ (256x64)
        gemm_tc<3,false,64><<<dim3(1, 2, Bsz*Hh), 256>>>(
            pS, pfqkv+256, pcomb, nullptr, 256,64,256, 256,384,128,
            131072,65536, 98304,64, 32768,64, 2, 0.1f);

        // a = comb @ Wp + x
        gemm_tc<1,false,128><<<dim3(1, ML/128, 1), 256>>>(
            pcomb, wp, pa, px, ML,128,128, 128,128,128,
            0,0,0,0,0,0, 1, 1.f);

        // FFN1 + GELU
        gemm_tc<2,false,128><<<dim3(2, ML/128, 1), 256>>>(
            pa, f1, ph, nullptr, ML,256,128, 128,256,256,
            0,0,0,0,0,0, 1, 1.f);

        // FFN2
        gemm_tc<0,false,128><<<dim3(1, ML/128, 1), 256>>>(
            ph, f2, px, nullptr, ML,128,256, 256,128,128,
            0,0,0,0,0,0, 1, 1.f);
    }

    gather_kernel<<<Bsz, 128>>>(lengths, out);
}